// round 4
// baseline (speedup 1.0000x reference)
#include <cuda_runtime.h>
#include <cuda_bf16.h>
#include <cstdint>

#define NUM_GRIDS 8

__device__ __forceinline__ float tanh_approx(float x) {
    float y;
    asm("tanh.approx.f32 %0, %1;" : "=f"(y) : "f"(x));
    return y;
}

// Each thread: load float4 of x, emit 4*8 = 32 contiguous output floats
// (8x STG.128). Output layout [..., G] puts the 8 basis values per input
// element contiguous, so per-thread output span is 128 B, fully coalesced.
__global__ __launch_bounds__(256)
void rswaf_kernel(const float4* __restrict__ x,
                  const float*  __restrict__ grid,
                  const float*  __restrict__ inv_den,
                  float4*       __restrict__ out,
                  int n4) {
    const int i = blockIdx.x * blockDim.x + threadIdx.x;
    if (i >= n4) return;

    const float inv = __ldg(inv_den);

    // Pre-scale grid by inv so inner loop is a single subtract before tanh:
    // (x - g) * inv == x*inv - g*inv
    float gs[NUM_GRIDS];
#pragma unroll
    for (int j = 0; j < NUM_GRIDS; j++)
        gs[j] = __ldg(grid + j) * inv;

    const float4 xv = __ldg(x + i);
    float xs[4] = {xv.x, xv.y, xv.z, xv.w};

    float4 o[NUM_GRIDS];           // 8 float4 = 32 floats = 4 elems x 8 grids
    float* op = reinterpret_cast<float*>(o);

#pragma unroll
    for (int e = 0; e < 4; e++) {
        const float xi = xs[e] * inv;
#pragma unroll
        for (int j = 0; j < NUM_GRIDS; j++) {
            const float th = tanh_approx(xi - gs[j]);
            op[e * NUM_GRIDS + j] = 1.0f - th * th;
        }
    }

    const long long base = (long long)i * NUM_GRIDS;
#pragma unroll
    for (int j = 0; j < NUM_GRIDS; j++)
        out[base + j] = o[j];
}

extern "C" void kernel_launch(void* const* d_in, const int* in_sizes, int n_in,
                              void* d_out, int out_size) {
    const float* x       = (const float*)d_in[0];   // [16,64,128,128] fp32
    const float* grid    = (const float*)d_in[1];   // [8] fp32
    const float* inv_den = (const float*)d_in[2];   // scalar fp32
    float* out = (float*)d_out;                     // [16,64,128,128,8] fp32

    const int n  = in_sizes[0];        // 16777216, divisible by 4
    const int n4 = n >> 2;             // 4194304 float4 loads

    const int threads = 256;
    const int blocks  = (n4 + threads - 1) / threads;   // 16384

    rswaf_kernel<<<blocks, threads>>>(
        (const float4*)x, grid, inv_den, (float4*)out, n4);
}

// round 5
// speedup vs baseline: 2.2642x; 2.2642x over previous
#include <cuda_runtime.h>
#include <cuda_bf16.h>
#include <cstdint>

#define NUM_GRIDS 8

__device__ __forceinline__ float tanh_approx(float x) {
    float y;
    asm("tanh.approx.f32 %0, %1;" : "=f"(y) : "f"(x));
    return y;
}

// Thread k owns OUTPUT float4 #k:
//   element  e = k >> 1          (each x element produces 8 outputs = 2 float4)
//   grid half  = (k & 1) * 4     (grids 0..3 or 4..7)
// Stores: consecutive lanes -> consecutive float4s = 512 B contiguous per warp
// per STG.128 (4 full sectors). Loads: lane pairs share x[e]; warp spans 64 B.
__global__ __launch_bounds__(256)
void rswaf_kernel(const float*  __restrict__ x,
                  const float*  __restrict__ grid,
                  const float*  __restrict__ inv_den,
                  float4*       __restrict__ out,
                  int nOut4) {
    const int k = blockIdx.x * blockDim.x + threadIdx.x;
    if (k >= nOut4) return;

    const float inv = __ldg(inv_den);

    const int e = k >> 1;
    const int h = (k & 1) << 2;            // 0 or 4

    // (x - g)*inv == x*inv - g*inv
    const float xi = __ldcs(x + e) * inv;

    const float g0 = __ldg(grid + h + 0) * inv;
    const float g1 = __ldg(grid + h + 1) * inv;
    const float g2 = __ldg(grid + h + 2) * inv;
    const float g3 = __ldg(grid + h + 3) * inv;

    const float t0 = tanh_approx(xi - g0);
    const float t1 = tanh_approx(xi - g1);
    const float t2 = tanh_approx(xi - g2);
    const float t3 = tanh_approx(xi - g3);

    float4 o;
    o.x = 1.0f - t0 * t0;
    o.y = 1.0f - t1 * t1;
    o.z = 1.0f - t2 * t2;
    o.w = 1.0f - t3 * t3;

    __stcs(out + k, o);                    // streaming: evict-first in L2
}

extern "C" void kernel_launch(void* const* d_in, const int* in_sizes, int n_in,
                              void* d_out, int out_size) {
    const float* x       = (const float*)d_in[0];   // [16,64,128,128] fp32
    const float* grid    = (const float*)d_in[1];   // [8] fp32
    const float* inv_den = (const float*)d_in[2];   // scalar fp32
    float* out = (float*)d_out;                     // [...,8] fp32

    const int nOut4 = out_size >> 2;                // 33,554,432 output float4s

    const int threads = 256;
    const int blocks  = (nOut4 + threads - 1) / threads;   // 131072

    rswaf_kernel<<<blocks, threads>>>(
        x, grid, inv_den, (float4*)out, nOut4);
}

// round 6
// speedup vs baseline: 2.8989x; 1.2804x over previous
#include <cuda_runtime.h>
#include <cuda_bf16.h>
#include <cstdint>

#define NUM_GRIDS 8

__device__ __forceinline__ float tanh_approx(float x) {
    float y;
    asm("tanh.approx.f32 %0, %1;" : "=f"(y) : "f"(x));
    return y;
}

// One thread per input element. Emits all 8 basis outputs with a single
// 256-bit store (STG.256): warp writes 1024 B fully contiguous per store
// instruction. Input: 1 scalar LDG per element, warp spans 128 B coalesced.
__global__ __launch_bounds__(256)
void rswaf_kernel(const float*  __restrict__ x,
                  const float4* __restrict__ grid,   // [8] floats = 2 float4
                  const float*  __restrict__ inv_den,
                  float*        __restrict__ out,
                  int n) {
    const int e = blockIdx.x * blockDim.x + threadIdx.x;
    if (e >= n) return;

    const float inv = __ldg(inv_den);

    // grid as two vector loads; pre-scale by inv: (x-g)*inv = x*inv - g*inv
    const float4 gA = __ldg(grid + 0);
    const float4 gB = __ldg(grid + 1);
    float gs[NUM_GRIDS] = {gA.x * inv, gA.y * inv, gA.z * inv, gA.w * inv,
                           gB.x * inv, gB.y * inv, gB.z * inv, gB.w * inv};

    const float xi = __ldcs(x + e) * inv;

    float r[NUM_GRIDS];
#pragma unroll
    for (int j = 0; j < NUM_GRIDS; j++) {
        const float th = tanh_approx(xi - gs[j]);
        r[j] = 1.0f - th * th;
    }

    float* dst = out + (long long)e * NUM_GRIDS;   // 32B-aligned
    asm volatile(
        "st.global.cs.v8.f32 [%0], {%1,%2,%3,%4,%5,%6,%7,%8};"
        :: "l"(dst),
           "f"(r[0]), "f"(r[1]), "f"(r[2]), "f"(r[3]),
           "f"(r[4]), "f"(r[5]), "f"(r[6]), "f"(r[7])
        : "memory");
}

extern "C" void kernel_launch(void* const* d_in, const int* in_sizes, int n_in,
                              void* d_out, int out_size) {
    const float* x       = (const float*)d_in[0];   // [16,64,128,128] fp32
    const float* grid    = (const float*)d_in[1];   // [8] fp32
    const float* inv_den = (const float*)d_in[2];   // scalar fp32
    float* out = (float*)d_out;                     // [...,8] fp32

    const int n = in_sizes[0];                      // 16,777,216 elements

    const int threads = 256;
    const int blocks  = (n + threads - 1) / threads;   // 65536

    rswaf_kernel<<<blocks, threads>>>(
        x, (const float4*)grid, inv_den, out, n);
}